// round 1
// baseline (speedup 1.0000x reference)
#include <cuda_runtime.h>
#include <cstdint>
#include <cstddef>

#define NB 8
#define NA 750000
#define PRE_NMS 4000
#define POST_NMS 1000
#define NMS_TH 0.7f
#define MIN_SIZE 0.001f
#define IMG_WF 1000.0f
#define IMG_HF 1000.0f
#define CAND_CAP 8192
#define WPR 64          /* mask words per row (63 used, 64 stride) */
#define BBOX_CLIP 4.135166556742356f   /* log(1000/16) */

// ---------------- scratch (static device allocations; no runtime alloc) -----
__device__ unsigned           g_hist_c[NB * 1024];
__device__ unsigned           g_hist_f[NB * 1024];
__device__ unsigned           g_zero8[NB];
__device__ unsigned           g_bucket_c[NB];
__device__ unsigned           g_above_c[NB];
__device__ unsigned           g_bucket_f[NB];
__device__ unsigned           g_above_f[NB];
__device__ int                g_cand_cnt[NB];
__device__ unsigned long long g_cand[NB * CAND_CAP];
__device__ float              g_score[NB * PRE_NMS];
__device__ int                g_idx[NB * PRE_NMS];
__device__ float4             g_box[NB * PRE_NMS];
__device__ float              g_prob[NB * PRE_NMS];
__device__ unsigned char      g_valid[NB * PRE_NMS];
__device__ unsigned long long g_mask[(size_t)NB * PRE_NMS * WPR];  // 16 MB
__device__ int                g_keptlist[NB * POST_NMS];
__device__ unsigned char      g_keepflag[NB * PRE_NMS];
__device__ int                g_nkeep[NB];

// monotone key: larger float -> larger unsigned
__device__ __forceinline__ unsigned fkey(float f) {
    unsigned u = __float_as_uint(f);
    return u ^ ((u & 0x80000000u) ? 0xFFFFFFFFu : 0x80000000u);
}
__device__ __forceinline__ float unkey(unsigned k) {
    return __uint_as_float((k & 0x80000000u) ? (k ^ 0x80000000u) : ~k);
}

// ---------------- K0: zero small scratch ------------------------------------
__global__ void k_zero() {
    int t = blockIdx.x * blockDim.x + threadIdx.x;
    for (int i = t; i < NB * 1024; i += gridDim.x * blockDim.x) {
        g_hist_c[i] = 0u;
        g_hist_f[i] = 0u;
    }
    if (t < NB) { g_cand_cnt[t] = 0; g_zero8[t] = 0u; }
}

// ---------------- K1: coarse 10-bit histogram -------------------------------
__global__ void k_hist_c(const float* __restrict__ obj) {
    __shared__ unsigned h[1024];
    for (int t = threadIdx.x; t < 1024; t += blockDim.x) h[t] = 0u;
    __syncthreads();
    int img = blockIdx.y;
    const float* o = obj + (size_t)img * NA;
    int stride = gridDim.x * blockDim.x;
    for (int i = blockIdx.x * blockDim.x + threadIdx.x; i < NA; i += stride)
        atomicAdd(&h[fkey(o[i]) >> 22], 1u);
    __syncthreads();
    for (int t = threadIdx.x; t < 1024; t += blockDim.x)
        if (h[t]) atomicAdd(&g_hist_c[img * 1024 + t], h[t]);
}

// ---------------- K2/K4: pick boundary bucket from a 1024-bin histogram -----
__global__ void k_select(int fine) {
    const unsigned* hist  = fine ? g_hist_f  : g_hist_c;
    const unsigned* basev = fine ? g_above_c : g_zero8;
    unsigned* out_b  = fine ? g_bucket_f : g_bucket_c;
    unsigned* out_ab = fine ? g_above_f  : g_above_c;
    int img = blockIdx.x, t = threadIdx.x;
    __shared__ unsigned sh[1024];
    sh[t] = hist[img * 1024 + (1023 - t)];   // reversed -> prefix = suffix sum
    __syncthreads();
    for (int off = 1; off < 1024; off <<= 1) {
        unsigned v = (t >= off) ? sh[t - off] : 0u;
        __syncthreads();
        sh[t] += v;
        __syncthreads();
    }
    unsigned base   = basev[img];
    unsigned needed = (unsigned)PRE_NMS - base;
    unsigned suff = sh[t];
    unsigned prev = (t == 0) ? 0u : sh[t - 1];
    if (suff >= needed && prev < needed) {
        out_b[img]  = 1023u - (unsigned)t;
        out_ab[img] = base + prev;
    }
}

// ---------------- K3: fine 10-bit histogram inside coarse boundary bucket ---
__global__ void k_hist_f(const float* __restrict__ obj) {
    __shared__ unsigned h[1024];
    for (int t = threadIdx.x; t < 1024; t += blockDim.x) h[t] = 0u;
    __syncthreads();
    int img = blockIdx.y;
    unsigned c = g_bucket_c[img];
    const float* o = obj + (size_t)img * NA;
    int stride = gridDim.x * blockDim.x;
    for (int i = blockIdx.x * blockDim.x + threadIdx.x; i < NA; i += stride) {
        unsigned key = fkey(o[i]);
        if ((key >> 22) == c) atomicAdd(&h[(key >> 12) & 1023u], 1u);
    }
    __syncthreads();
    for (int t = threadIdx.x; t < 1024; t += blockDim.x)
        if (h[t]) atomicAdd(&g_hist_f[img * 1024 + t], h[t]);
}

// ---------------- K5: compact candidates above threshold --------------------
__global__ void k_compact(const float* __restrict__ obj) {
    int img = blockIdx.y;
    unsigned T = (g_bucket_c[img] << 10) | g_bucket_f[img];
    const float* o = obj + (size_t)img * NA;
    int stride = gridDim.x * blockDim.x;
    for (int i = blockIdx.x * blockDim.x + threadIdx.x; i < NA; i += stride) {
        unsigned key = fkey(o[i]);
        if ((key >> 12) >= T) {
            int p = atomicAdd(&g_cand_cnt[img], 1);
            if (p < CAND_CAP)
                g_cand[img * CAND_CAP + p] =
                    ((unsigned long long)key << 32) | (unsigned)(~(unsigned)i);
        }
    }
}

// ---------------- K6: bitonic sort candidates, emit top-4000 ----------------
__global__ void k_sort() {
    extern __shared__ unsigned long long s[];
    int img = blockIdx.x;
    int cnt = g_cand_cnt[img];
    if (cnt > CAND_CAP) cnt = CAND_CAP;
    for (int t = threadIdx.x; t < CAND_CAP; t += blockDim.x)
        s[t] = (t < cnt) ? g_cand[img * CAND_CAP + t] : 0ull;
    __syncthreads();
    for (unsigned k = 2; k <= CAND_CAP; k <<= 1) {
        for (unsigned j = k >> 1; j > 0; j >>= 1) {
            for (unsigned idx = threadIdx.x; idx < CAND_CAP; idx += blockDim.x) {
                unsigned ixj = idx ^ j;
                if (ixj > idx) {
                    unsigned long long a = s[idx], b = s[ixj];
                    bool blk = ((idx & k) == 0u);     // descending overall
                    if (blk ? (a < b) : (a > b)) { s[idx] = b; s[ixj] = a; }
                }
            }
            __syncthreads();
        }
    }
    for (int t = threadIdx.x; t < PRE_NMS; t += blockDim.x) {
        unsigned long long key = s[t];
        g_score[img * PRE_NMS + t] = unkey((unsigned)(key >> 32));
        g_idx[img * PRE_NMS + t]   = (int)(~(unsigned)key);
    }
}

// ---------------- K7: decode + clip + valid + sigmoid -----------------------
__global__ void k_decode(const float* __restrict__ deltas,
                         const float* __restrict__ anchors) {
    int img = blockIdx.y;
    int t = blockIdx.x * blockDim.x + threadIdx.x;
    if (t >= PRE_NMS) return;
    int idx = g_idx[img * PRE_NMS + t];
    float4 a = ((const float4*)anchors)[idx];
    float4 d = ((const float4*)deltas)[(size_t)img * NA + idx];
    float w = a.z - a.x, h = a.w - a.y;
    float cx = a.x + 0.5f * w, cy = a.y + 0.5f * h;
    float dw = fminf(d.z, BBOX_CLIP), dh = fminf(d.w, BBOX_CLIP);
    float pcx = d.x * w + cx, pcy = d.y * h + cy;
    float pw = expf(dw) * w, ph = expf(dh) * h;
    float x1 = pcx - 0.5f * pw, y1 = pcy - 0.5f * ph;
    float x2 = pcx + 0.5f * pw, y2 = pcy + 0.5f * ph;
    x1 = fminf(fmaxf(x1, 0.f), IMG_WF);
    y1 = fminf(fmaxf(y1, 0.f), IMG_HF);
    x2 = fminf(fmaxf(x2, 0.f), IMG_WF);
    y2 = fminf(fmaxf(y2, 0.f), IMG_HF);
    g_box[img * PRE_NMS + t] = make_float4(x1, y1, x2, y2);
    g_valid[img * PRE_NMS + t] =
        ((x2 - x1) >= MIN_SIZE && (y2 - y1) >= MIN_SIZE) ? 1 : 0;
    float sc = g_score[img * PRE_NMS + t];
    g_prob[img * PRE_NMS + t] = 1.f / (1.f + expf(-sc));
}

// ---------------- K8: IoU suppression bitmask (upper triangle) --------------
__global__ void k_iou() {
    int img = blockIdx.z, rb = blockIdx.y, cb = blockIdx.x;
    __shared__ float4 cbox[64];
    int col0 = cb * 64;
    int c = col0 + threadIdx.x;
    cbox[threadIdx.x] = (c < PRE_NMS) ? g_box[img * PRE_NMS + c]
                                      : make_float4(0, 0, 0, 0);
    __syncthreads();
    int row = rb * 64 + threadIdx.x;
    if (row >= PRE_NMS) return;
    float4 rbx = g_box[img * PRE_NMS + row];
    float rarea = (rbx.z - rbx.x) * (rbx.w - rbx.y);
    unsigned long long m = 0ull;
    if (col0 + 63 > row) {
        for (int j = 0; j < 64; j++) {
            int col = col0 + j;
            if (col > row && col < PRE_NMS) {
                float4 cbx = cbox[j];
                float xx1 = fmaxf(rbx.x, cbx.x), yy1 = fmaxf(rbx.y, cbx.y);
                float xx2 = fminf(rbx.z, cbx.z), yy2 = fminf(rbx.w, cbx.w);
                float ww = fmaxf(xx2 - xx1, 0.f), hh = fmaxf(yy2 - yy1, 0.f);
                float inter = ww * hh;
                float carea = (cbx.z - cbx.x) * (cbx.w - cbx.y);
                float uni = rarea + carea - inter;
                float iou = inter / fmaxf(uni, 1e-9f);
                if (iou > NMS_TH) m |= (1ull << j);
            }
        }
    }
    g_mask[((size_t)img * PRE_NMS + row) * WPR + cb] = m;
}

// ---------------- K9: greedy NMS scan, 1 warp/image, 8-row prefetch ---------
__global__ void k_nms() {
    int img = blockIdx.x, lane = threadIdx.x;
    const unsigned char* v = g_valid + img * PRE_NMS;
    unsigned long long r0 = 0ull, r1 = 0ull;   // remv: lane holds words lane, 32+lane
    for (int b = 0; b < 64; b++) {
        int i0 = lane * 64 + b;
        if (i0 < PRE_NMS && !v[i0]) r0 |= (1ull << b);
        int i1 = (32 + lane) * 64 + b;
        if (i1 < PRE_NMS && !v[i1]) r1 |= (1ull << b);
    }
    const unsigned long long* M = g_mask + (size_t)img * PRE_NMS * WPR;
    unsigned long long q0[8], q1[8];
#pragma unroll
    for (int u = 0; u < 8; u++) {
        q0[u] = M[(size_t)u * WPR + lane];
        q1[u] = (lane < 31) ? M[(size_t)u * WPR + 32 + lane] : 0ull;
    }
    int n = 0;
    bool done = false;
    for (int base = 0; base < PRE_NMS && !done; base += 8) {
#pragma unroll
        for (int u = 0; u < 8; u++) {
            int i = base + u;
            int w = i >> 6, b = i & 63;
            unsigned long long word =
                (w < 32) ? __shfl_sync(0xffffffffu, r0, w)
                         : __shfl_sync(0xffffffffu, r1, w - 32);
            bool keep = ((word >> b) & 1ull) == 0ull;
            if (keep) {
                r0 |= q0[u];
                r1 |= q1[u];
                if (lane == 0) g_keptlist[img * POST_NMS + n] = i;
                n++;
            }
            if (lane == 0) g_keepflag[img * PRE_NMS + i] = keep ? 1 : 0;
            if (n >= POST_NMS) { done = true; break; }
        }
        if (!done) {
            int nb = base + 8;
#pragma unroll
            for (int u = 0; u < 8; u++) {
                int i = nb + u;
                if (i < PRE_NMS) {
                    q0[u] = M[(size_t)i * WPR + lane];
                    q1[u] = (lane < 31) ? M[(size_t)i * WPR + 32 + lane] : 0ull;
                } else { q0[u] = 0ull; q1[u] = 0ull; }
            }
        }
    }
    if (lane == 0) g_nkeep[img] = n;
}

// ---------------- K10: assemble output --------------------------------------
// layout assumed: [proposals (8,1000,4) f32][scores (8,1000) f32]
__global__ void k_out(float* __restrict__ out) {
    int img = blockIdx.x, tid = threadIdx.x;
    int n = g_nkeep[img];
    int lim = n < POST_NMS ? n : POST_NMS;
    for (int s = tid; s < lim; s += blockDim.x) {
        int i = g_keptlist[img * POST_NMS + s];
        ((float4*)out)[img * POST_NMS + s] = g_box[img * PRE_NMS + i];
        out[NB * POST_NMS * 4 + img * POST_NMS + s] = g_prob[img * PRE_NMS + i];
    }
    if (n >= POST_NMS) return;
    // fill with non-kept indices ascending, score = -inf (matches top_k tie rule)
    __shared__ unsigned sh[1024];
    unsigned base = 0;
    for (int chunk = 0; chunk < PRE_NMS; chunk += 1024) {
        int i = chunk + tid;
        unsigned f = (i < PRE_NMS && g_keepflag[img * PRE_NMS + i] == 0) ? 1u : 0u;
        sh[tid] = f;
        __syncthreads();
        for (int off = 1; off < 1024; off <<= 1) {
            unsigned vv = (tid >= off) ? sh[tid - off] : 0u;
            __syncthreads();
            sh[tid] += vv;
            __syncthreads();
        }
        unsigned excl = sh[tid] - f;
        int slot = n + (int)(base + excl);
        if (f && slot < POST_NMS) {
            ((float4*)out)[img * POST_NMS + slot] = g_box[img * PRE_NMS + i];
            out[NB * POST_NMS * 4 + img * POST_NMS + slot] =
                __int_as_float(0xff800000);  // -inf
        }
        base += sh[1023];
        __syncthreads();
    }
}

// ---------------- host ------------------------------------------------------
extern "C" void kernel_launch(void* const* d_in, const int* in_sizes, int n_in,
                              void* d_out, int out_size) {
    const float* obj     = (const float*)d_in[0];   // (8, 750000)
    const float* deltas  = (const float*)d_in[1];   // (8, 750000, 4)
    const float* anchors = (const float*)d_in[2];   // (750000, 4)
    float* out = (float*)d_out;

    k_zero<<<8, 1024>>>();
    k_hist_c<<<dim3(144, NB), 256>>>(obj);
    k_select<<<NB, 1024>>>(0);
    k_hist_f<<<dim3(144, NB), 256>>>(obj);
    k_select<<<NB, 1024>>>(1);
    k_compact<<<dim3(144, NB), 256>>>(obj);

    cudaFuncSetAttribute(k_sort, cudaFuncAttributeMaxDynamicSharedMemorySize,
                         CAND_CAP * (int)sizeof(unsigned long long));
    k_sort<<<NB, 1024, CAND_CAP * sizeof(unsigned long long)>>>();

    k_decode<<<dim3((PRE_NMS + 255) / 256, NB), 256>>>(deltas, anchors);
    k_iou<<<dim3(63, 63, NB), 64>>>();
    k_nms<<<NB, 32>>>();
    k_out<<<NB, 1024>>>(out);
}